// round 4
// baseline (speedup 1.0000x reference)
#include <cuda_runtime.h>
#include <cuda_bf16.h>

// SSIM loss: inputs (16,3,512,512) fp32 x2, output scalar fp32.
// 48 planes of 512x512, same separable 11-tap Gaussian (sigma=1.5) on
// 5 fields (a, b, a^2, b^2, ab), then per-pixel SSIM map + global mean.
//
// Block = 32x64 output tile, 256 threads.
//  Phase A: vertical conv from global (coalesced, register-sliding, 168 threads)
//           -> smem V[5][64][43] (stride 43 = conflict-free).
//  Phase B: horizontal conv from smem (register-sliding, 256 threads, 8 cols each)
//           + SSIM epilogue + block reduction -> atomicAdd(double).

#define W_IMG 512
#define H_IMG 512
#define PLANE (512 * 512)
#define TX 32
#define TY 64
#define SV_STRIDE 43
#define SV_FIELD (TY * SV_STRIDE)   // 2752 floats per field
#define SMEM_FLOATS (5 * SV_FIELD + 32)
#define SMEM_BYTES (SMEM_FLOATS * 4)
#define N_PIX 12582912.0            // 16*3*512*512

// Gaussian window, sigma=1.5, ws=11, normalized (matches fp64->fp32 reference
// weights to ~1e-7 relative). Function-local so it's valid in device code and
// constant-folds into FFMA immediates after full unroll.
#define DECL_GW()                                                       \
    const float GW[11] = {                                              \
        0.00102838f, 0.00759876f, 0.03600077f, 0.10936069f, 0.21300554f,\
        0.26601173f,                                                    \
        0.21300554f, 0.10936069f, 0.03600077f, 0.00759876f, 0.00102838f }

__device__ double g_accum;

__device__ __forceinline__ float clip01(float v) {
    // fmaxf(NaN, 0) -> 0, so this also implements nan_to_num.
    return fminf(fmaxf(v, 0.0f), 1.0f);
}

__global__ void ssim_init_kernel() { g_accum = 0.0; }

__global__ void ssim_fini_kernel(float* __restrict__ out) {
    out[0] = (float)(1.0 - g_accum / N_PIX);
}

extern __shared__ float sV[];  // [5][TY][SV_STRIDE] + 32 reduction slots

__global__ __launch_bounds__(256)
void ssim_main_kernel(const float* __restrict__ img1,
                      const float* __restrict__ img2) {
    DECL_GW();
    const int tid   = threadIdx.x;
    const int plane = blockIdx.z;
    const int cx0   = blockIdx.x * TX;
    const int cy0   = blockIdx.y * TY;
    const float* __restrict__ A = img1 + (size_t)plane * PLANE;
    const float* __restrict__ B = img2 + (size_t)plane * PLANE;

    // ---------------- Phase A: vertical 11-tap conv ----------------
    // 42 columns (TX+10 halo) x 4 strips of 16 output rows = 168 items.
    if (tid < 168) {
        const int col   = tid % 42;       // 0..41 (halo cols)
        const int strip = tid / 42;       // 0..3
        const int r0    = strip * 16;     // first output row of strip
        const int gc    = cx0 + col - 5;  // global col
        const bool okc  = ((unsigned)gc < (unsigned)W_IMG);

        float acc[5][16];
        #pragma unroll
        for (int f = 0; f < 5; f++)
            #pragma unroll
            for (int r = 0; r < 16; r++) acc[f][r] = 0.0f;

        #pragma unroll
        for (int q = 0; q < 26; q++) {
            const int gr = cy0 + r0 + q - 5;   // global row
            float a = 0.0f, b = 0.0f;
            if (okc && (unsigned)gr < (unsigned)H_IMG) {
                const int idx = gr * W_IMG + gc;
                a = A[idx];
                b = B[idx];
            }
            a = clip01(a);
            b = clip01(b);
            const float a2 = a * a, b2 = b * b, ab = a * b;
            // input row q contributes to output rows rr in [q-10, q] /\ [0,16)
            #pragma unroll
            for (int rr = (q > 10 ? q - 10 : 0); rr <= (q < 15 ? q : 15); rr++) {
                const float w = GW[q - rr];   // compile-time constant -> FFMA-imm
                acc[0][rr] = fmaf(a,  w, acc[0][rr]);
                acc[1][rr] = fmaf(b,  w, acc[1][rr]);
                acc[2][rr] = fmaf(a2, w, acc[2][rr]);
                acc[3][rr] = fmaf(b2, w, acc[3][rr]);
                acc[4][rr] = fmaf(ab, w, acc[4][rr]);
            }
        }
        #pragma unroll
        for (int rr = 0; rr < 16; rr++) {
            const int row = r0 + rr;
            #pragma unroll
            for (int f = 0; f < 5; f++)
                sV[f * SV_FIELD + row * SV_STRIDE + col] = acc[f][rr];
        }
    }
    __syncthreads();

    // ---------------- Phase B: horizontal 11-tap conv + SSIM ----------------
    // 64 rows x 4 groups of 8 output cols = 256 items (perfect balance).
    const int orow = tid >> 2;     // 0..63
    const int grp  = tid & 3;      // 0..3
    const int base = orow * SV_STRIDE + grp * 8;

    float acc[5][8];
    #pragma unroll
    for (int f = 0; f < 5; f++)
        #pragma unroll
        for (int o = 0; o < 8; o++) acc[f][o] = 0.0f;

    #pragma unroll
    for (int p = 0; p < 18; p++) {
        float v[5];
        #pragma unroll
        for (int f = 0; f < 5; f++)
            v[f] = sV[f * SV_FIELD + base + p];
        // V column p contributes to outputs o in [p-10, p] /\ [0,8)
        #pragma unroll
        for (int o = (p > 10 ? p - 10 : 0); o <= (p < 7 ? p : 7); o++) {
            const float w = GW[p - o];
            #pragma unroll
            for (int f = 0; f < 5; f++)
                acc[f][o] = fmaf(v[f], w, acc[f][o]);
        }
    }

    // SSIM epilogue + thread-local sum
    const float C1 = 0.000101f;   // 0.01^2 + 1e-6
    const float C2 = 0.000901f;   // 0.03^2 + 1e-6
    float lsum = 0.0f;
    #pragma unroll
    for (int o = 0; o < 8; o++) {
        const float mu1 = acc[0][o], mu2 = acc[1][o];
        const float mu1s = mu1 * mu1;
        const float mu2s = mu2 * mu2;
        const float mu12 = mu1 * mu2;
        float s1 = acc[2][o] - mu1s;
        float s2 = acc[3][o] - mu2s;
        const float s12 = acc[4][o] - mu12;
        s1 = fminf(fmaxf(s1, 1e-6f), 1e6f);
        s2 = fminf(fmaxf(s2, 1e-6f), 1e6f);
        const float num = (2.0f * mu12 + C1) * (2.0f * s12 + C2);
        const float den = (mu1s + mu2s + C1) * (s1 + s2 + C2);
        lsum += __fdividef(num, den);
    }

    // ---------------- Reduction ----------------
    #pragma unroll
    for (int off = 16; off > 0; off >>= 1)
        lsum += __shfl_xor_sync(0xffffffffu, lsum, off);

    float* red = sV + 5 * SV_FIELD;
    const int warp = tid >> 5;
    const int lane = tid & 31;
    if (lane == 0) red[warp] = lsum;
    __syncthreads();
    if (warp == 0) {
        float v = (lane < 8) ? red[lane] : 0.0f;
        #pragma unroll
        for (int off = 4; off > 0; off >>= 1)
            v += __shfl_xor_sync(0xffffffffu, v, off);
        if (lane == 0) atomicAdd(&g_accum, (double)v);
    }
}

extern "C" void kernel_launch(void* const* d_in, const int* in_sizes, int n_in,
                              void* d_out, int out_size) {
    const float* img1 = (const float*)d_in[0];
    const float* img2 = (const float*)d_in[1];
    float* out = (float*)d_out;

    cudaFuncSetAttribute(ssim_main_kernel,
                         cudaFuncAttributeMaxDynamicSharedMemorySize,
                         SMEM_BYTES);

    ssim_init_kernel<<<1, 1>>>();
    dim3 grid(W_IMG / TX, H_IMG / TY, 48);  // 16 x 8 x 48 = 6144 blocks
    ssim_main_kernel<<<grid, 256, SMEM_BYTES>>>(img1, img2);
    ssim_fini_kernel<<<1, 1>>>(out);
}